// round 15
// baseline (speedup 1.0000x reference)
#include <cuda_runtime.h>
#include <cuda_bf16.h>
#include <math.h>
#include <stdint.h>

#define BB 4
#define TT 2048
#define CC 1024
#define HH 128
#define SCALE 0.08838834764831845f  // 1/sqrt(128)

#define NS   8     // split-K segments for out_kernel
#define SLEN 256   // keys per segment

#define PAD  40    // smem row stride (bf16), conflict-free for ldmatrix
#define PADT 136   // smem row stride (bf16) for 128-wide transposed tiles
#define PADS 132   // smem row stride (fp32) for staged ST chunks

#define TILE_B   10240u                 // one padded 128x32 bf16 tile
#define STAGE_B  (4u * TILE_B)          // st: A_hi|A_lo|B_hi|B_lo (128-row A)
#define SMEM_DYN (2u * STAGE_B)         // st: 2 stages = 81920 B

#define ATILE64_B 5120u                 // qkv: 64x32 A tile (padded)
#define STAGE64_B (2u * ATILE64_B + 2u * TILE_B)   // 30720 B
#define SMEM_QKV  (2u * STAGE64_B)      // 61440 B (round-11 proven)

// out_mma dynamic smem layout (bytes)
#define O_PHI    0u
#define O_PLO    8704u                  // 32*PADT*2
#define O_VHI    17408u
#define O_VLO    26112u
#define O_STF    34816u                 // fp32 ST stages
#define O_STF_SZ 16896u                 // 32*PADS*4
#define SMEM_OUT (O_STF + 2u * O_STF_SZ)   // 68608 B

#define NXB ((BB * TT * CC) / 1024)     // prep: x blocks (4 elems/thread)
#define NWB ((3 * HH * CC) / 256)       // prep: W blocks

// ---------------------------------------------------------------------------
// Device-global scratch
// ---------------------------------------------------------------------------
__device__ __nv_bfloat16 g_vhi[BB * TT * HH];
__device__ __nv_bfloat16 g_vlo[BB * TT * HH];
__device__ __nv_bfloat16 g_qhi[BB * TT * HH];
__device__ __nv_bfloat16 g_qlo[BB * TT * HH];
__device__ __nv_bfloat16 g_khi[BB * TT * HH];
__device__ __nv_bfloat16 g_klo[BB * TT * HH];
__device__ __nv_bfloat16 g_xhi[(size_t)BB * TT * CC];
__device__ __nv_bfloat16 g_xlo[(size_t)BB * TT * CC];
__device__ __nv_bfloat16 g_wthi[3 * HH * CC];   // [y][n][k] = W[k][n]
__device__ __nv_bfloat16 g_wtlo[3 * HH * CC];
__device__ float g_st[(size_t)BB * TT * TT];
__device__ float g_pm[BB * 16 * TT];            // per-(b, t-tile, s) partial max
__device__ float g_pd[BB * 16 * TT];            // per-(b, t-tile, s) partial sumexp
__device__ float g_part[(size_t)NS * BB * TT * HH];
__device__ int   g_cnt[BB * 16];                // per-(b, t-tile) arrival counter

// ---------------------------------------------------------------------------
// PTX helpers
// ---------------------------------------------------------------------------
__device__ __forceinline__ uint32_t smem_u32(const void* p) {
    uint32_t a;
    asm("{ .reg .u64 t; cvta.to.shared.u64 t, %1; cvt.u32.u64 %0, t; }"
        : "=r"(a) : "l"(p));
    return a;
}

__device__ __forceinline__ void ldsm4(uint32_t r[4], uint32_t addr) {
    asm volatile("ldmatrix.sync.aligned.m8n8.x4.shared.b16 {%0,%1,%2,%3}, [%4];"
                 : "=r"(r[0]), "=r"(r[1]), "=r"(r[2]), "=r"(r[3]) : "r"(addr));
}

__device__ __forceinline__ void ldsm4t(uint32_t r[4], uint32_t addr) {
    asm volatile("ldmatrix.sync.aligned.m8n8.x4.trans.shared.b16 {%0,%1,%2,%3}, [%4];"
                 : "=r"(r[0]), "=r"(r[1]), "=r"(r[2]), "=r"(r[3]) : "r"(addr));
}

__device__ __forceinline__ void mma16816(float d[4], const uint32_t a[4],
                                         uint32_t b0, uint32_t b1) {
    asm volatile(
        "mma.sync.aligned.m16n8k16.row.col.f32.bf16.bf16.f32 "
        "{%0,%1,%2,%3}, {%4,%5,%6,%7}, {%8,%9}, {%0,%1,%2,%3};"
        : "+f"(d[0]), "+f"(d[1]), "+f"(d[2]), "+f"(d[3])
        : "r"(a[0]), "r"(a[1]), "r"(a[2]), "r"(a[3]), "r"(b0), "r"(b1));
}

__device__ __forceinline__ void cp16(uint32_t saddr, const void* gptr) {
    asm volatile("cp.async.cg.shared.global [%0], [%1], 16;"
                 :: "r"(saddr), "l"(gptr));
}
#define CP_COMMIT() asm volatile("cp.async.commit_group;" ::: "memory")
#define CP_WAIT1()  asm volatile("cp.async.wait_group 1;" ::: "memory")
#define CP_WAIT0()  asm volatile("cp.async.wait_group 0;" ::: "memory")

// online-softmax merge; m always finite (sentinel -1e30), v may be -inf
__device__ __forceinline__ void sm_merge(float& m, float& d, float m2, float d2) {
    float mn = fmaxf(m, m2);
    d = d * __expf(m - mn) + d2 * __expf(m2 - mn);
    m = mn;
}

__device__ __forceinline__ uint32_t split_pack(float v0, float v1,
                                               uint32_t& lopack) {
    __nv_bfloat16 h0 = __float2bfloat16(v0);
    __nv_bfloat16 h1 = __float2bfloat16(v1);
    __nv_bfloat16 l0 = __float2bfloat16(v0 - __bfloat162float(h0));
    __nv_bfloat16 l1 = __float2bfloat16(v1 - __bfloat162float(h1));
    lopack = (uint32_t)__bfloat16_as_ushort(l0)
           | ((uint32_t)__bfloat16_as_ushort(l1) << 16);
    return (uint32_t)__bfloat16_as_ushort(h0)
         | ((uint32_t)__bfloat16_as_ushort(h1) << 16);
}

// ---- 128-row-A loaders/compute (st kernel; proven) ----
__device__ __forceinline__ void load4_async(
    const __nv_bfloat16* __restrict__ Ahi, const __nv_bfloat16* __restrict__ Alo,
    const __nv_bfloat16* __restrict__ Bhi, const __nv_bfloat16* __restrict__ Blo,
    int ld, uint32_t sb, int tid)
{
    #pragma unroll
    for (int i = 0; i < 2; i++) {
        int v = tid + i * 256;
        int r = v >> 2, c = v & 3;
        uint32_t so = (uint32_t)(r * PAD + c * 8) * 2;
        size_t   go = (size_t)r * ld + c * 8;
        cp16(sb + so,              Ahi + go);
        cp16(sb + TILE_B + so,     Alo + go);
        cp16(sb + 2 * TILE_B + so, Bhi + go);
        cp16(sb + 3 * TILE_B + so, Blo + go);
    }
}

__device__ __forceinline__ void gemm_chunk(uint32_t sbase, int lane, int wm, int wn,
                                           float acc[4][4][4]) {
    #pragma unroll
    for (int ks = 0; ks < 2; ks++) {
        const int k0 = ks * 16;
        uint32_t a_hi[4][4], a_lo[4][4], b_hi[2][4], b_lo[2][4];

        const int arow = lane & 15;
        const int acol = k0 + ((lane >> 4) << 3);
        #pragma unroll
        for (int i = 0; i < 4; i++) {
            uint32_t off = (uint32_t)((wm * 64 + i * 16 + arow) * PAD + acol) * 2;
            ldsm4(a_hi[i], sbase + off);
            ldsm4(a_lo[i], sbase + TILE_B + off);
        }

        const int brow = (lane & 7) + ((lane >> 4) << 3);
        const int bcol = k0 + ((lane >> 3) & 1) * 8;
        #pragma unroll
        for (int j = 0; j < 2; j++) {
            uint32_t off = (uint32_t)((wn * 32 + j * 16 + brow) * PAD + bcol) * 2;
            ldsm4(b_hi[j], sbase + 2 * TILE_B + off);
            ldsm4(b_lo[j], sbase + 3 * TILE_B + off);
        }

        #pragma unroll
        for (int i = 0; i < 4; i++) {
            #pragma unroll
            for (int jn = 0; jn < 4; jn++) {
                uint32_t b0h = b_hi[jn >> 1][(jn & 1) * 2];
                uint32_t b1h = b_hi[jn >> 1][(jn & 1) * 2 + 1];
                uint32_t b0l = b_lo[jn >> 1][(jn & 1) * 2];
                uint32_t b1l = b_lo[jn >> 1][(jn & 1) * 2 + 1];
                mma16816(acc[i][jn], a_hi[i], b0h, b1h);   // hh
                mma16816(acc[i][jn], a_lo[i], b0h, b1h);   // lh
                mma16816(acc[i][jn], a_hi[i], b0l, b1l);   // hl
            }
        }
    }
}

// ---- 64-row-A loaders/compute (qkv kernel; round-11 proven) ----
__device__ __forceinline__ void load4_async64(
    const __nv_bfloat16* __restrict__ Ahi, const __nv_bfloat16* __restrict__ Alo,
    const __nv_bfloat16* __restrict__ Bhi, const __nv_bfloat16* __restrict__ Blo,
    int ldA, int ldB, uint32_t sb, int tid)
{
    {
        int r = tid >> 2, c = tid & 3;
        uint32_t so = (uint32_t)(r * PAD + c * 8) * 2;
        size_t   go = (size_t)r * ldA + c * 8;
        cp16(sb + so,             Ahi + go);
        cp16(sb + ATILE64_B + so, Alo + go);
    }
    #pragma unroll
    for (int i = 0; i < 2; i++) {
        int v = tid + i * 256;
        int r = v >> 2, c = v & 3;
        uint32_t so = (uint32_t)(r * PAD + c * 8) * 2;
        size_t   go = (size_t)r * ldB + c * 8;
        cp16(sb + 2 * ATILE64_B + so,          Bhi + go);
        cp16(sb + 2 * ATILE64_B + TILE_B + so, Blo + go);
    }
}

__device__ __forceinline__ void gemm_chunk64(uint32_t sbase, int lane, int wm, int wn,
                                             float acc[2][4][4]) {
    #pragma unroll
    for (int ks = 0; ks < 2; ks++) {
        const int k0 = ks * 16;
        uint32_t a_hi[2][4], a_lo[2][4], b_hi[2][4], b_lo[2][4];

        const int arow = lane & 15;
        const int acol = k0 + ((lane >> 4) << 3);
        #pragma unroll
        for (int i = 0; i < 2; i++) {
            uint32_t off = (uint32_t)((wm * 32 + i * 16 + arow) * PAD + acol) * 2;
            ldsm4(a_hi[i], sbase + off);
            ldsm4(a_lo[i], sbase + ATILE64_B + off);
        }

        const int brow = (lane & 7) + ((lane >> 4) << 3);
        const int bcol = k0 + ((lane >> 3) & 1) * 8;
        #pragma unroll
        for (int j = 0; j < 2; j++) {
            uint32_t off = (uint32_t)((wn * 32 + j * 16 + brow) * PAD + bcol) * 2;
            ldsm4(b_hi[j], sbase + 2 * ATILE64_B + off);
            ldsm4(b_lo[j], sbase + 2 * ATILE64_B + TILE_B + off);
        }

        #pragma unroll
        for (int i = 0; i < 2; i++) {
            #pragma unroll
            for (int jn = 0; jn < 4; jn++) {
                uint32_t b0h = b_hi[jn >> 1][(jn & 1) * 2];
                uint32_t b1h = b_hi[jn >> 1][(jn & 1) * 2 + 1];
                uint32_t b0l = b_lo[jn >> 1][(jn & 1) * 2];
                uint32_t b1l = b_lo[jn >> 1][(jn & 1) * 2 + 1];
                mma16816(acc[i][jn], a_hi[i], b0h, b1h);   // hh
                mma16816(acc[i][jn], a_lo[i], b0h, b1h);   // lh
                mma16816(acc[i][jn], a_hi[i], b0l, b1l);   // hl
            }
        }
    }
}

// ---------------------------------------------------------------------------
// P0: fused input splits + counter reset.
// blocks [0, NXB): x (float4/thread); [NXB, NXB+NWB): W; last block: counters.
// ---------------------------------------------------------------------------
__global__ __launch_bounds__(256) void prep_kernel(
    const float* __restrict__ x,
    const float* __restrict__ Wq, const float* __restrict__ Wk,
    const float* __restrict__ Wv)
{
    if (blockIdx.x < NXB) {
        size_t i = ((size_t)blockIdx.x * 256 + threadIdx.x) * 4;
        float4 f = *reinterpret_cast<const float4*>(x + i);
        uint2 hi, lo;
        hi.x = split_pack(f.x, f.y, lo.x);
        hi.y = split_pack(f.z, f.w, lo.y);
        *reinterpret_cast<uint2*>(g_xhi + i) = hi;
        *reinterpret_cast<uint2*>(g_xlo + i) = lo;
    } else if (blockIdx.x < NXB + NWB) {
        int i = (blockIdx.x - NXB) * 256 + threadIdx.x;
        int k = i & (CC - 1);
        int n = (i >> 10) & (HH - 1);
        int y = i >> 17;
        const float* W = (y == 0) ? Wq : (y == 1) ? Wk : Wv;
        float f = W[(size_t)k * HH + n];
        __nv_bfloat16 hi = __float2bfloat16(f);
        g_wthi[i] = hi;
        g_wtlo[i] = __float2bfloat16(f - __bfloat162float(hi));
    } else {
        if (threadIdx.x < BB * 16) g_cnt[threadIdx.x] = 0;
    }
}

// ---------------------------------------------------------------------------
// K1: QKV projection, 64x128 tiles, 2-stage cp.async (round-11 proven).
// ---------------------------------------------------------------------------
__global__ __launch_bounds__(256) void qkv_mma_kernel()
{
    extern __shared__ __align__(16) uint8_t dynsmem[];

    const int tid  = threadIdx.x;
    const int wid  = tid >> 5;
    const int lane = tid & 31;
    const int wm   = wid & 1;
    const int wn   = wid >> 1;
    const int y    = blockIdx.y;
    const int row0 = blockIdx.x * 64;
    const uint32_t sb0 = smem_u32(dynsmem);

    const __nv_bfloat16* Ahi = g_xhi + (size_t)row0 * CC;
    const __nv_bfloat16* Alo = g_xlo + (size_t)row0 * CC;
    const __nv_bfloat16* Bhi = g_wthi + (size_t)y * HH * CC;
    const __nv_bfloat16* Blo = g_wtlo + (size_t)y * HH * CC;

    float acc[2][4][4] = {};
    const int NC = CC / 32;

    load4_async64(Ahi, Alo, Bhi, Blo, CC, CC, sb0, tid);
    CP_COMMIT();

    for (int kc = 0; kc < NC; kc++) {
        if (kc + 1 < NC) {
            const int k1 = (kc + 1) * 32;
            load4_async64(Ahi + k1, Alo + k1, Bhi + k1, Blo + k1, CC, CC,
                          sb0 + ((kc + 1) & 1) * STAGE64_B, tid);
            CP_COMMIT();
            CP_WAIT1();
        } else {
            CP_WAIT0();
        }
        __syncthreads();
        gemm_chunk64(sb0 + (kc & 1) * STAGE64_B, lane, wm, wn, acc);
        __syncthreads();
    }

    uint32_t* smu = reinterpret_cast<uint32_t*>(dynsmem);
    const int g = lane >> 2;
    const int q = lane & 3;
    #pragma unroll
    for (int i = 0; i < 2; i++) {
        #pragma unroll
        for (int jn = 0; jn < 4; jn++) {
            #pragma unroll
            for (int erow = 0; erow < 2; erow++) {
                int row  = wm * 32 + i * 16 + g + erow * 8;
                int colu = wn * 16 + jn * 4 + q;
                uint32_t lp;
                uint32_t hp = split_pack(acc[i][jn][erow * 2],
                                         acc[i][jn][erow * 2 + 1], lp);
                smu[row * 68 + colu] = hp;
                smu[64 * 68 + row * 68 + colu] = lp;
            }
        }
    }
    __syncthreads();

    __nv_bfloat16* dhi = (y == 0) ? g_qhi : (y == 1) ? g_khi : g_vhi;
    __nv_bfloat16* dlo = (y == 0) ? g_qlo : (y == 1) ? g_klo : g_vlo;
    const uint4* s4 = reinterpret_cast<const uint4*>(dynsmem);
    #pragma unroll
    for (int it = 0; it < 4; it++) {
        int v = tid + it * 256;
        int row = v >> 4, c4 = v & 15;
        *reinterpret_cast<uint4*>(dhi + (size_t)(row0 + row) * HH + c4 * 8) =
            s4[row * 17 + c4];
        *reinterpret_cast<uint4*>(dlo + (size_t)(row0 + row) * HH + c4 * 8) =
            s4[64 * 17 + row * 17 + c4];
    }
}

// ---------------------------------------------------------------------------
// K2: ST tile + fused softmax partials. Triangular grid = (136, B) (proven).
// ---------------------------------------------------------------------------
__global__ __launch_bounds__(256) void st_mma_kernel()
{
    int ti = blockIdx.x;
    int jt = (int)((sqrtf(8.0f * ti + 1.0f) - 1.0f) * 0.5f);
    while ((jt + 1) * (jt + 2) / 2 <= ti) jt++;
    while (jt * (jt + 1) / 2 > ti) jt--;
    const int js = ti - jt * (jt + 1) / 2;

    const int b  = blockIdx.y;
    const int t0 = jt * 128;
    const int s0 = js * 128;

    extern __shared__ __align__(16) uint8_t dynsmem[];

    const int tid  = threadIdx.x;
    const int wid  = tid >> 5;
    const int lane = tid & 31;
    const int wm   = wid & 1;
    const int wn   = wid >> 1;
    const uint32_t sb0 = smem_u32(dynsmem);

    const __nv_bfloat16* Ahi = g_khi + ((size_t)b * TT + s0) * HH;
    const __nv_bfloat16* Alo = g_klo + ((size_t)b * TT + s0) * HH;
    const __nv_bfloat16* Bhi = g_qhi + ((size_t)b * TT + t0) * HH;
    const __nv_bfloat16* Blo = g_qlo + ((size_t)b * TT + t0) * HH;

    float acc[4][4][4] = {};
    const int NC = HH / 32;

    load4_async(Ahi, Alo, Bhi, Blo, HH, sb0, tid);
    CP_COMMIT();

    for (int kc = 0; kc < NC; kc++) {
        if (kc + 1 < NC) {
            const int k1 = (kc + 1) * 32;
            load4_async(Ahi + k1, Alo + k1, Bhi + k1, Blo + k1, HH,
                        sb0 + ((kc + 1) & 1) * STAGE_B, tid);
            CP_COMMIT();
            CP_WAIT1();
        } else {
            CP_WAIT0();
        }
        __syncthreads();
        gemm_chunk(sb0 + (kc & 1) * STAGE_B, lane, wm, wn, acc);
        __syncthreads();
    }

    float* stb = g_st + (size_t)b * TT * TT;
    const int g  = lane >> 2;
    const int c2 = (lane & 3) * 2;

    float pm[8], pd[8];
    #pragma unroll
    for (int k8 = 0; k8 < 8; k8++) { pm[k8] = -1e30f; pd[k8] = 0.0f; }

    #pragma unroll
    for (int i = 0; i < 4; i++) {
        #pragma unroll
        for (int jn = 0; jn < 4; jn++) {
            int ssb = s0 + wm * 64 + i * 16 + g;
            int tt0 = t0 + wn * 32 + jn * 8 + c2;
            #pragma unroll
            for (int erow = 0; erow < 2; erow++) {
                int ss = ssb + erow * 8;
                float2 w;
                w.x = (tt0     >= ss) ? acc[i][jn][erow * 2]     * SCALE : -INFINITY;
                w.y = (tt0 + 1 >= ss) ? acc[i][jn][erow * 2 + 1] * SCALE : -INFINITY;
                *reinterpret_cast<float2*>(&stb[(size_t)ss * TT + tt0]) = w;
                int k8 = i * 2 + erow;
                float mn = fmaxf(pm[k8], fmaxf(w.x, w.y));
                pd[k8] = pd[k8] * __expf(pm[k8] - mn)
                       + __expf(w.x - mn) + __expf(w.y - mn);
                pm[k8] = mn;
            }
        }
    }

    #pragma unroll
    for (int k8 = 0; k8 < 8; k8++) {
        #pragma unroll
        for (int off = 1; off <= 2; off <<= 1) {
            float m2 = __shfl_xor_sync(0xffffffffu, pm[k8], off);
            float d2 = __shfl_xor_sync(0xffffffffu, pd[k8], off);
            sm_merge(pm[k8], pd[k8], m2, d2);
        }
    }

    float* smf = reinterpret_cast<float*>(dynsmem);
    if ((lane & 3) == 0) {
        #pragma unroll
        for (int k8 = 0; k8 < 8; k8++) {
            int r = wm * 64 + (k8 >> 1) * 16 + g + (k8 & 1) * 8;
            smf[r * 4 + wn]       = pm[k8];
            smf[512 + r * 4 + wn] = pd[k8];
        }
    }
    __syncthreads();
    if (tid < 128) {
        float m = -1e30f, d = 0.0f;
        #pragma unroll
        for (int w = 0; w < 4; w++)
            sm_merge(m, d, smf[tid * 4 + w], smf[512 + tid * 4 + w]);
        size_t o = (((size_t)b * 16 + jt) << 11) + s0 + tid;
        g_pm[o] = m;
        g_pd[o] = d;
    }
}

// ---------------------------------------------------------------------------
// K4: split-K out partials + fused final reduction (threadfence-reduction).
// grid = (T/128, NS, B), dyn smem 68608 B, 2 CTAs/SM.
// ---------------------------------------------------------------------------
__global__ __launch_bounds__(256, 2) void out_mma_kernel(float* __restrict__ out)
{
    const int b  = blockIdx.z;
    const int t0 = blockIdx.x * 128;
    const int js = blockIdx.y;
    const int jt = blockIdx.x;

    const int s_begin = js * SLEN;
    const int s_end_v = (js + 1) * SLEN;
    const int s_end   = (s_end_v < t0 + 128) ? s_end_v : (t0 + 128);
    if (s_begin >= s_end) return;
    const int nact = (jt + 2) >> 1;   // # active segments for this t-tile

    extern __shared__ __align__(16) uint8_t dynsmem[];
    __nv_bfloat16* smem = reinterpret_cast<__nv_bfloat16*>(dynsmem);
    __shared__ float sm_m[SLEN], sm_rd[SLEN];
    __shared__ int s_last;

    const float* stb = g_st + (size_t)b * TT * TT;
    const __nv_bfloat16* vhi = g_vhi + (size_t)b * TT * HH;
    const __nv_bfloat16* vlo = g_vlo + (size_t)b * TT * HH;
    float* part = g_part + ((size_t)js * BB + b) * TT * HH;

    const int tid  = threadIdx.x;
    const int wid  = tid >> 5;
    const int lane = tid & 31;
    const int wm   = wid & 1;
    const int wn   = wid >> 1;
    const uint32_t sbase = smem_u32(dynsmem);

    auto load_st = [&](int sc, int st01) {
        uint32_t sfb = sbase + O_STF + (uint32_t)st01 * O_STF_SZ;
        #pragma unroll
        for (int i = 0; i < 4; i++) {
            int v = tid + i * 256;
            int r = v >> 5, c = v & 31;
            cp16(sfb + (uint32_t)(r * PADS + c * 4) * 4,
                 stb + (size_t)(sc + r) * TT + t0 + c * 4);
        }
    };

    load_st(s_begin, 0);
    CP_COMMIT();
    {
        int s = s_begin + tid;
        if (s < s_end) {
            float m = -1e30f, d = 0.0f;
            for (int j = s >> 7; j < 16; j++) {
                size_t o = (((size_t)b * 16 + j) << 11) + s;
                sm_merge(m, d, g_pm[o], g_pd[o]);
            }
            sm_m[tid]  = m;
            sm_rd[tid] = 1.0f / d;
        }
    }

    float acc[4][4][4] = {};
    const int nch = (s_end - s_begin) >> 5;

    for (int ch = 0; ch < nch; ch++) {
        const int sc = s_begin + ch * 32;
        const int lbase = sc - s_begin;
        const int stage = ch & 1;

        CP_WAIT0();
        __syncthreads();

        if (ch + 1 < nch) {
            load_st(sc + 32, stage ^ 1);
            CP_COMMIT();
        }

        #pragma unroll
        for (int i = 0; i < 2; i++) {
            int v = tid + i * 256;
            int r = v >> 4, c = v & 15;
            *reinterpret_cast<uint4*>(smem + O_VHI / 2 + r * PADT + c * 8) =
                *reinterpret_cast<const uint4*>(vhi + (size_t)(sc + r) * HH + c * 8);
            *reinterpret_cast<uint4*>(smem + O_VLO / 2 + r * PADT + c * 8) =
                *reinterpret_cast<const uint4*>(vlo + (size_t)(sc + r) * HH + c * 8);
        }
        const float* stf = reinterpret_cast<const float*>(
            dynsmem + O_STF + (uint32_t)stage * O_STF_SZ);
        #pragma unroll
        for (int i = 0; i < 16; i++) {
            int idx = tid + i * 256;
            int ss = idx >> 7, ttl = idx & 127;
            float val = stf[ss * PADS + ttl];
            float p = __expf(val - sm_m[lbase + ss]) * sm_rd[lbase + ss];
            __nv_bfloat16 hi = __float2bfloat16(p);
            __nv_bfloat16 lo = __float2bfloat16(p - __bfloat162float(hi));
            smem[O_PHI / 2 + ss * PADT + ttl] = hi;
            smem[O_PLO / 2 + ss * PADT + ttl] = lo;
        }
        __syncthreads();

        #pragma unroll
        for (int ks = 0; ks < 2; ks++) {
            const int k0 = ks * 16;
            uint32_t a_hi[4][4], a_lo[4][4], b_hi[2][4], b_lo[2][4];

            const int arow = k0 + (lane & 7) + ((lane >> 4) << 3);
            const int acoff = ((lane >> 3) & 1) * 8;
            #pragma unroll
            for (int i = 0; i < 4; i++) {
                uint32_t off = (uint32_t)(arow * PADT + wm * 64 + i * 16 + acoff) * 2;
                ldsm4t(a_hi[i], sbase + O_PHI + off);
                ldsm4t(a_lo[i], sbase + O_PLO + off);
            }

            const int brow = k0 + (lane & 7) + (((lane >> 3) & 1) << 3);
            const int bcoff = ((lane >> 4) << 3);
            #pragma unroll
            for (int j = 0; j < 2; j++) {
                uint32_t off = (uint32_t)(brow * PADT + wn * 32 + j * 16 + bcoff) * 2;
                ldsm4t(b_hi[j], sbase + O_VHI + off);
                ldsm4t(b_lo[j], sbase + O_VLO + off);
            }

            #pragma unroll
            for (int i = 0; i < 4; i++) {
                #pragma unroll
                for (int jn = 0; jn < 4; jn++) {
                    uint32_t b0h = b_hi[jn >> 1][(jn & 1) * 2];
                    uint32_t b1h = b_hi[jn >> 1][(jn & 1) * 2 + 1];
                    uint32_t b0l = b_lo[jn >> 1][(jn & 1) * 2];
                    uint32_t b1l = b_lo[jn >> 1][(jn & 1) * 2 + 1];
                    mma16816(acc[i][jn], a_hi[i], b0h, b1h);   // hh
                    mma16816(acc[i][jn], a_lo[i], b0h, b1h);   // lh
                    mma16816(acc[i][jn], a_hi[i], b0l, b1l);   // hl
                }
            }
        }
    }

    const int g  = lane >> 2;
    const int c2 = (lane & 3) * 2;
    float* outb = out + ((size_t)b * TT) * HH;

    if (nact == 1) {
        // only segment for this tile: write result directly
        #pragma unroll
        for (int i = 0; i < 4; i++) {
            #pragma unroll
            for (int jn = 0; jn < 4; jn++) {
                int t = t0 + wm * 64 + i * 16 + g;
                int h = wn * 32 + jn * 8 + c2;
                #pragma unroll
                for (int erow = 0; erow < 2; erow++) {
                    float2 w;
                    w.x = acc[i][jn][erow * 2];
                    w.y = acc[i][jn][erow * 2 + 1];
                    *reinterpret_cast<float2*>(
                        &outb[(size_t)(t + erow * 8) * HH + h]) = w;
                }
            }
        }
        return;
    }

    // write partial
    #pragma unroll
    for (int i = 0; i < 4; i++) {
        #pragma unroll
        for (int jn = 0; jn < 4; jn++) {
            int t = t0 + wm * 64 + i * 16 + g;
            int h = wn * 32 + jn * 8 + c2;
            #pragma unroll
            for (int erow = 0; erow < 2; erow++) {
                float2 w;
                w.x = acc[i][jn][erow * 2];
                w.y = acc[i][jn][erow * 2 + 1];
                *reinterpret_cast<float2*>(
                    &part[(size_t)(t + erow * 8) * HH + h]) = w;
            }
        }
    }
    __threadfence();
    if (tid == 0) {
        int old = atomicAdd(&g_cnt[b * 16 + jt], 1);
        s_last = (old == nact - 1);
    }
    __syncthreads();
    if (!s_last) return;
    __threadfence();

    // last arrival: reduce all partials in fixed j-order (deterministic)
    #pragma unroll
    for (int i = 0; i < 4; i++) {
        #pragma unroll
        for (int jn = 0; jn < 4; jn++) {
            int t = t0 + wm * 64 + i * 16 + g;
            int h = wn * 32 + jn * 8 + c2;
            #pragma unroll
            for (int erow = 0; erow < 2; erow++) {
                size_t eo = (size_t)(t + erow * 8) * HH + h;
                float2 sum = make_float2(0.0f, 0.0f);
                for (int j = 0; j < nact; j++) {
                    float2 w = *reinterpret_cast<const float2*>(
                        &g_part[((size_t)j * BB + b) * TT * HH + eo]);
                    sum.x += w.x;
                    sum.y += w.y;
                }
                *reinterpret_cast<float2*>(&outb[eo]) = sum;
            }
        }
    }
}

extern "C" void kernel_launch(void* const* d_in, const int* in_sizes, int n_in,
                              void* d_out, int out_size)
{
    const float* x  = (const float*)d_in[0];
    const float* Wq = (const float*)d_in[1];
    const float* Wk = (const float*)d_in[2];
    const float* Wv = (const float*)d_in[3];
    float* out = (float*)d_out;

    cudaFuncSetAttribute(qkv_mma_kernel,
                         cudaFuncAttributeMaxDynamicSharedMemorySize, SMEM_QKV);
    cudaFuncSetAttribute(st_mma_kernel,
                         cudaFuncAttributeMaxDynamicSharedMemorySize, SMEM_DYN);
    cudaFuncSetAttribute(out_mma_kernel,
                         cudaFuncAttributeMaxDynamicSharedMemorySize, SMEM_OUT);

    prep_kernel<<<NXB + NWB + 1, 256>>>(x, Wq, Wk, Wv);
    qkv_mma_kernel<<<dim3((BB * TT) / 64, 3), 256, SMEM_QKV>>>();
    st_mma_kernel<<<dim3(136, BB), 256, SMEM_DYN>>>();
    out_mma_kernel<<<dim3(TT / 128, NS, BB), 256, SMEM_OUT>>>(out);
}

// round 16
// speedup vs baseline: 1.1388x; 1.1388x over previous
#include <cuda_runtime.h>
#include <cuda_bf16.h>
#include <math.h>
#include <stdint.h>

#define BB 4
#define TT 2048
#define CC 1024
#define HH 128
#define SCALE 0.08838834764831845f  // 1/sqrt(128)

#define NS   8     // split-K segments for out_kernel
#define SLEN 256   // keys per segment

#define PAD  40    // smem row stride (bf16), conflict-free for ldmatrix
#define PADT 136   // smem row stride (bf16) for 128-wide transposed tiles
#define PADS 132   // smem row stride (fp32) for staged ST chunks

#define TILE_B   10240u                 // one padded 128x32 bf16 tile
#define STAGE_B  (4u * TILE_B)          // st: A_hi|A_lo|B_hi|B_lo (128-row A)
#define SMEM_DYN (2u * STAGE_B)         // st: 2 stages = 81920 B

#define ATILE64_B 5120u                 // qkv: 64x32 A tile (padded)
#define STAGE64_B (2u * ATILE64_B + 2u * TILE_B)   // 30720 B
#define SMEM_QKV  (2u * STAGE64_B)      // 61440 B (round-11 proven)

// out_mma dynamic smem layout (bytes)
#define O_PHI    0u
#define O_PLO    8704u                  // 32*PADT*2
#define O_VHI    17408u
#define O_VLO    26112u
#define O_STF    34816u                 // fp32 ST stages
#define O_STF_SZ 16896u                 // 32*PADS*4
#define SMEM_OUT (O_STF + 2u * O_STF_SZ)   // 68608 B

#define NXB ((BB * TT * CC) / 1024)     // prep: x blocks (4 elems/thread)
#define NWB ((3 * HH * CC) / 256)       // prep: W blocks

// ---------------------------------------------------------------------------
// Device-global scratch
// ---------------------------------------------------------------------------
__device__ __nv_bfloat16 g_vhi[BB * TT * HH];
__device__ __nv_bfloat16 g_vlo[BB * TT * HH];
__device__ __nv_bfloat16 g_qhi[BB * TT * HH];
__device__ __nv_bfloat16 g_qlo[BB * TT * HH];
__device__ __nv_bfloat16 g_khi[BB * TT * HH];
__device__ __nv_bfloat16 g_klo[BB * TT * HH];
__device__ __nv_bfloat16 g_xhi[(size_t)BB * TT * CC];
__device__ __nv_bfloat16 g_xlo[(size_t)BB * TT * CC];
__device__ __nv_bfloat16 g_wthi[3 * HH * CC];   // [y][n][k] = W[k][n]
__device__ __nv_bfloat16 g_wtlo[3 * HH * CC];
__device__ float g_st[(size_t)BB * TT * TT];
__device__ float g_pm[BB * 16 * TT];            // per-(b, t-tile, s) partial max
__device__ float g_pd[BB * 16 * TT];            // per-(b, t-tile, s) partial sumexp
__device__ float g_part[(size_t)NS * BB * TT * HH];

// ---------------------------------------------------------------------------
// PTX helpers
// ---------------------------------------------------------------------------
__device__ __forceinline__ uint32_t smem_u32(const void* p) {
    uint32_t a;
    asm("{ .reg .u64 t; cvta.to.shared.u64 t, %1; cvt.u32.u64 %0, t; }"
        : "=r"(a) : "l"(p));
    return a;
}

__device__ __forceinline__ void ldsm4(uint32_t r[4], uint32_t addr) {
    asm volatile("ldmatrix.sync.aligned.m8n8.x4.shared.b16 {%0,%1,%2,%3}, [%4];"
                 : "=r"(r[0]), "=r"(r[1]), "=r"(r[2]), "=r"(r[3]) : "r"(addr));
}

__device__ __forceinline__ void ldsm4t(uint32_t r[4], uint32_t addr) {
    asm volatile("ldmatrix.sync.aligned.m8n8.x4.trans.shared.b16 {%0,%1,%2,%3}, [%4];"
                 : "=r"(r[0]), "=r"(r[1]), "=r"(r[2]), "=r"(r[3]) : "r"(addr));
}

__device__ __forceinline__ void mma16816(float d[4], const uint32_t a[4],
                                         uint32_t b0, uint32_t b1) {
    asm volatile(
        "mma.sync.aligned.m16n8k16.row.col.f32.bf16.bf16.f32 "
        "{%0,%1,%2,%3}, {%4,%5,%6,%7}, {%8,%9}, {%0,%1,%2,%3};"
        : "+f"(d[0]), "+f"(d[1]), "+f"(d[2]), "+f"(d[3])
        : "r"(a[0]), "r"(a[1]), "r"(a[2]), "r"(a[3]), "r"(b0), "r"(b1));
}

__device__ __forceinline__ void cp16(uint32_t saddr, const void* gptr) {
    asm volatile("cp.async.cg.shared.global [%0], [%1], 16;"
                 :: "r"(saddr), "l"(gptr));
}
#define CP_COMMIT() asm volatile("cp.async.commit_group;" ::: "memory")
#define CP_WAIT1()  asm volatile("cp.async.wait_group 1;" ::: "memory")
#define CP_WAIT0()  asm volatile("cp.async.wait_group 0;" ::: "memory")

// online-softmax merge; m always finite (sentinel -1e30), v may be -inf
__device__ __forceinline__ void sm_merge(float& m, float& d, float m2, float d2) {
    float mn = fmaxf(m, m2);
    d = d * __expf(m - mn) + d2 * __expf(m2 - mn);
    m = mn;
}

__device__ __forceinline__ uint32_t split_pack(float v0, float v1,
                                               uint32_t& lopack) {
    __nv_bfloat16 h0 = __float2bfloat16(v0);
    __nv_bfloat16 h1 = __float2bfloat16(v1);
    __nv_bfloat16 l0 = __float2bfloat16(v0 - __bfloat162float(h0));
    __nv_bfloat16 l1 = __float2bfloat16(v1 - __bfloat162float(h1));
    lopack = (uint32_t)__bfloat16_as_ushort(l0)
           | ((uint32_t)__bfloat16_as_ushort(l1) << 16);
    return (uint32_t)__bfloat16_as_ushort(h0)
         | ((uint32_t)__bfloat16_as_ushort(h1) << 16);
}

// ---- 128-row-A loaders/compute (st kernel; proven) ----
__device__ __forceinline__ void load4_async(
    const __nv_bfloat16* __restrict__ Ahi, const __nv_bfloat16* __restrict__ Alo,
    const __nv_bfloat16* __restrict__ Bhi, const __nv_bfloat16* __restrict__ Blo,
    int ld, uint32_t sb, int tid)
{
    #pragma unroll
    for (int i = 0; i < 2; i++) {
        int v = tid + i * 256;
        int r = v >> 2, c = v & 3;
        uint32_t so = (uint32_t)(r * PAD + c * 8) * 2;
        size_t   go = (size_t)r * ld + c * 8;
        cp16(sb + so,              Ahi + go);
        cp16(sb + TILE_B + so,     Alo + go);
        cp16(sb + 2 * TILE_B + so, Bhi + go);
        cp16(sb + 3 * TILE_B + so, Blo + go);
    }
}

__device__ __forceinline__ void gemm_chunk(uint32_t sbase, int lane, int wm, int wn,
                                           float acc[4][4][4]) {
    #pragma unroll
    for (int ks = 0; ks < 2; ks++) {
        const int k0 = ks * 16;
        uint32_t a_hi[4][4], a_lo[4][4], b_hi[2][4], b_lo[2][4];

        const int arow = lane & 15;
        const int acol = k0 + ((lane >> 4) << 3);
        #pragma unroll
        for (int i = 0; i < 4; i++) {
            uint32_t off = (uint32_t)((wm * 64 + i * 16 + arow) * PAD + acol) * 2;
            ldsm4(a_hi[i], sbase + off);
            ldsm4(a_lo[i], sbase + TILE_B + off);
        }

        const int brow = (lane & 7) + ((lane >> 4) << 3);
        const int bcol = k0 + ((lane >> 3) & 1) * 8;
        #pragma unroll
        for (int j = 0; j < 2; j++) {
            uint32_t off = (uint32_t)((wn * 32 + j * 16 + brow) * PAD + bcol) * 2;
            ldsm4(b_hi[j], sbase + 2 * TILE_B + off);
            ldsm4(b_lo[j], sbase + 3 * TILE_B + off);
        }

        #pragma unroll
        for (int i = 0; i < 4; i++) {
            #pragma unroll
            for (int jn = 0; jn < 4; jn++) {
                uint32_t b0h = b_hi[jn >> 1][(jn & 1) * 2];
                uint32_t b1h = b_hi[jn >> 1][(jn & 1) * 2 + 1];
                uint32_t b0l = b_lo[jn >> 1][(jn & 1) * 2];
                uint32_t b1l = b_lo[jn >> 1][(jn & 1) * 2 + 1];
                mma16816(acc[i][jn], a_hi[i], b0h, b1h);   // hh
                mma16816(acc[i][jn], a_lo[i], b0h, b1h);   // lh
                mma16816(acc[i][jn], a_hi[i], b0l, b1l);   // hl
            }
        }
    }
}

// ---- 64-row-A loaders/compute (qkv kernel; round-11 proven) ----
__device__ __forceinline__ void load4_async64(
    const __nv_bfloat16* __restrict__ Ahi, const __nv_bfloat16* __restrict__ Alo,
    const __nv_bfloat16* __restrict__ Bhi, const __nv_bfloat16* __restrict__ Blo,
    int ldA, int ldB, uint32_t sb, int tid)
{
    {
        int r = tid >> 2, c = tid & 3;
        uint32_t so = (uint32_t)(r * PAD + c * 8) * 2;
        size_t   go = (size_t)r * ldA + c * 8;
        cp16(sb + so,             Ahi + go);
        cp16(sb + ATILE64_B + so, Alo + go);
    }
    #pragma unroll
    for (int i = 0; i < 2; i++) {
        int v = tid + i * 256;
        int r = v >> 2, c = v & 3;
        uint32_t so = (uint32_t)(r * PAD + c * 8) * 2;
        size_t   go = (size_t)r * ldB + c * 8;
        cp16(sb + 2 * ATILE64_B + so,          Bhi + go);
        cp16(sb + 2 * ATILE64_B + TILE_B + so, Blo + go);
    }
}

__device__ __forceinline__ void gemm_chunk64(uint32_t sbase, int lane, int wm, int wn,
                                             float acc[2][4][4]) {
    #pragma unroll
    for (int ks = 0; ks < 2; ks++) {
        const int k0 = ks * 16;
        uint32_t a_hi[2][4], a_lo[2][4], b_hi[2][4], b_lo[2][4];

        const int arow = lane & 15;
        const int acol = k0 + ((lane >> 4) << 3);
        #pragma unroll
        for (int i = 0; i < 2; i++) {
            uint32_t off = (uint32_t)((wm * 32 + i * 16 + arow) * PAD + acol) * 2;
            ldsm4(a_hi[i], sbase + off);
            ldsm4(a_lo[i], sbase + ATILE64_B + off);
        }

        const int brow = (lane & 7) + ((lane >> 4) << 3);
        const int bcol = k0 + ((lane >> 3) & 1) * 8;
        #pragma unroll
        for (int j = 0; j < 2; j++) {
            uint32_t off = (uint32_t)((wn * 32 + j * 16 + brow) * PAD + bcol) * 2;
            ldsm4(b_hi[j], sbase + 2 * ATILE64_B + off);
            ldsm4(b_lo[j], sbase + 2 * ATILE64_B + TILE_B + off);
        }

        #pragma unroll
        for (int i = 0; i < 2; i++) {
            #pragma unroll
            for (int jn = 0; jn < 4; jn++) {
                uint32_t b0h = b_hi[jn >> 1][(jn & 1) * 2];
                uint32_t b1h = b_hi[jn >> 1][(jn & 1) * 2 + 1];
                uint32_t b0l = b_lo[jn >> 1][(jn & 1) * 2];
                uint32_t b1l = b_lo[jn >> 1][(jn & 1) * 2 + 1];
                mma16816(acc[i][jn], a_hi[i], b0h, b1h);   // hh
                mma16816(acc[i][jn], a_lo[i], b0h, b1h);   // lh
                mma16816(acc[i][jn], a_hi[i], b0l, b1l);   // hl
            }
        }
    }
}

// ---------------------------------------------------------------------------
// P0: fused input splits (x float4/thread, then W blocks)
// ---------------------------------------------------------------------------
__global__ __launch_bounds__(256) void prep_kernel(
    const float* __restrict__ x,
    const float* __restrict__ Wq, const float* __restrict__ Wk,
    const float* __restrict__ Wv)
{
    if (blockIdx.x < NXB) {
        size_t i = ((size_t)blockIdx.x * 256 + threadIdx.x) * 4;
        float4 f = *reinterpret_cast<const float4*>(x + i);
        uint2 hi, lo;
        hi.x = split_pack(f.x, f.y, lo.x);
        hi.y = split_pack(f.z, f.w, lo.y);
        *reinterpret_cast<uint2*>(g_xhi + i) = hi;
        *reinterpret_cast<uint2*>(g_xlo + i) = lo;
    } else {
        int i = (blockIdx.x - NXB) * 256 + threadIdx.x;
        int k = i & (CC - 1);
        int n = (i >> 10) & (HH - 1);
        int y = i >> 17;
        const float* W = (y == 0) ? Wq : (y == 1) ? Wk : Wv;
        float f = W[(size_t)k * HH + n];
        __nv_bfloat16 hi = __float2bfloat16(f);
        g_wthi[i] = hi;
        g_wtlo[i] = __float2bfloat16(f - __bfloat162float(hi));
    }
}

// ---------------------------------------------------------------------------
// K1: QKV projection, 64x128 tiles, 2-stage cp.async (round-11 proven).
// ---------------------------------------------------------------------------
__global__ __launch_bounds__(256) void qkv_mma_kernel()
{
    extern __shared__ __align__(16) uint8_t dynsmem[];

    const int tid  = threadIdx.x;
    const int wid  = tid >> 5;
    const int lane = tid & 31;
    const int wm   = wid & 1;
    const int wn   = wid >> 1;
    const int y    = blockIdx.y;
    const int row0 = blockIdx.x * 64;
    const uint32_t sb0 = smem_u32(dynsmem);

    const __nv_bfloat16* Ahi = g_xhi + (size_t)row0 * CC;
    const __nv_bfloat16* Alo = g_xlo + (size_t)row0 * CC;
    const __nv_bfloat16* Bhi = g_wthi + (size_t)y * HH * CC;
    const __nv_bfloat16* Blo = g_wtlo + (size_t)y * HH * CC;

    float acc[2][4][4] = {};
    const int NC = CC / 32;

    load4_async64(Ahi, Alo, Bhi, Blo, CC, CC, sb0, tid);
    CP_COMMIT();

    for (int kc = 0; kc < NC; kc++) {
        if (kc + 1 < NC) {
            const int k1 = (kc + 1) * 32;
            load4_async64(Ahi + k1, Alo + k1, Bhi + k1, Blo + k1, CC, CC,
                          sb0 + ((kc + 1) & 1) * STAGE64_B, tid);
            CP_COMMIT();
            CP_WAIT1();
        } else {
            CP_WAIT0();
        }
        __syncthreads();
        gemm_chunk64(sb0 + (kc & 1) * STAGE64_B, lane, wm, wn, acc);
        __syncthreads();
    }

    uint32_t* smu = reinterpret_cast<uint32_t*>(dynsmem);
    const int g = lane >> 2;
    const int q = lane & 3;
    #pragma unroll
    for (int i = 0; i < 2; i++) {
        #pragma unroll
        for (int jn = 0; jn < 4; jn++) {
            #pragma unroll
            for (int erow = 0; erow < 2; erow++) {
                int row  = wm * 32 + i * 16 + g + erow * 8;
                int colu = wn * 16 + jn * 4 + q;
                uint32_t lp;
                uint32_t hp = split_pack(acc[i][jn][erow * 2],
                                         acc[i][jn][erow * 2 + 1], lp);
                smu[row * 68 + colu] = hp;
                smu[64 * 68 + row * 68 + colu] = lp;
            }
        }
    }
    __syncthreads();

    __nv_bfloat16* dhi = (y == 0) ? g_qhi : (y == 1) ? g_khi : g_vhi;
    __nv_bfloat16* dlo = (y == 0) ? g_qlo : (y == 1) ? g_klo : g_vlo;
    const uint4* s4 = reinterpret_cast<const uint4*>(dynsmem);
    #pragma unroll
    for (int it = 0; it < 4; it++) {
        int v = tid + it * 256;
        int row = v >> 4, c4 = v & 15;
        *reinterpret_cast<uint4*>(dhi + (size_t)(row0 + row) * HH + c4 * 8) =
            s4[row * 17 + c4];
        *reinterpret_cast<uint4*>(dlo + (size_t)(row0 + row) * HH + c4 * 8) =
            s4[64 * 17 + row * 17 + c4];
    }
}

// ---------------------------------------------------------------------------
// K2: ST tile + fused softmax partials. Triangular grid = (136, B) (proven).
// ---------------------------------------------------------------------------
__global__ __launch_bounds__(256) void st_mma_kernel()
{
    int ti = blockIdx.x;
    int jt = (int)((sqrtf(8.0f * ti + 1.0f) - 1.0f) * 0.5f);
    while ((jt + 1) * (jt + 2) / 2 <= ti) jt++;
    while (jt * (jt + 1) / 2 > ti) jt--;
    const int js = ti - jt * (jt + 1) / 2;

    const int b  = blockIdx.y;
    const int t0 = jt * 128;
    const int s0 = js * 128;

    extern __shared__ __align__(16) uint8_t dynsmem[];

    const int tid  = threadIdx.x;
    const int wid  = tid >> 5;
    const int lane = tid & 31;
    const int wm   = wid & 1;
    const int wn   = wid >> 1;
    const uint32_t sb0 = smem_u32(dynsmem);

    const __nv_bfloat16* Ahi = g_khi + ((size_t)b * TT + s0) * HH;
    const __nv_bfloat16* Alo = g_klo + ((size_t)b * TT + s0) * HH;
    const __nv_bfloat16* Bhi = g_qhi + ((size_t)b * TT + t0) * HH;
    const __nv_bfloat16* Blo = g_qlo + ((size_t)b * TT + t0) * HH;

    float acc[4][4][4] = {};
    const int NC = HH / 32;

    load4_async(Ahi, Alo, Bhi, Blo, HH, sb0, tid);
    CP_COMMIT();

    for (int kc = 0; kc < NC; kc++) {
        if (kc + 1 < NC) {
            const int k1 = (kc + 1) * 32;
            load4_async(Ahi + k1, Alo + k1, Bhi + k1, Blo + k1, HH,
                        sb0 + ((kc + 1) & 1) * STAGE_B, tid);
            CP_COMMIT();
            CP_WAIT1();
        } else {
            CP_WAIT0();
        }
        __syncthreads();
        gemm_chunk(sb0 + (kc & 1) * STAGE_B, lane, wm, wn, acc);
        __syncthreads();
    }

    float* stb = g_st + (size_t)b * TT * TT;
    const int g  = lane >> 2;
    const int c2 = (lane & 3) * 2;

    float pm[8], pd[8];
    #pragma unroll
    for (int k8 = 0; k8 < 8; k8++) { pm[k8] = -1e30f; pd[k8] = 0.0f; }

    #pragma unroll
    for (int i = 0; i < 4; i++) {
        #pragma unroll
        for (int jn = 0; jn < 4; jn++) {
            int ssb = s0 + wm * 64 + i * 16 + g;
            int tt0 = t0 + wn * 32 + jn * 8 + c2;
            #pragma unroll
            for (int erow = 0; erow < 2; erow++) {
                int ss = ssb + erow * 8;
                float2 w;
                w.x = (tt0     >= ss) ? acc[i][jn][erow * 2]     * SCALE : -INFINITY;
                w.y = (tt0 + 1 >= ss) ? acc[i][jn][erow * 2 + 1] * SCALE : -INFINITY;
                *reinterpret_cast<float2*>(&stb[(size_t)ss * TT + tt0]) = w;
                int k8 = i * 2 + erow;
                float mn = fmaxf(pm[k8], fmaxf(w.x, w.y));
                pd[k8] = pd[k8] * __expf(pm[k8] - mn)
                       + __expf(w.x - mn) + __expf(w.y - mn);
                pm[k8] = mn;
            }
        }
    }

    #pragma unroll
    for (int k8 = 0; k8 < 8; k8++) {
        #pragma unroll
        for (int off = 1; off <= 2; off <<= 1) {
            float m2 = __shfl_xor_sync(0xffffffffu, pm[k8], off);
            float d2 = __shfl_xor_sync(0xffffffffu, pd[k8], off);
            sm_merge(pm[k8], pd[k8], m2, d2);
        }
    }

    float* smf = reinterpret_cast<float*>(dynsmem);
    if ((lane & 3) == 0) {
        #pragma unroll
        for (int k8 = 0; k8 < 8; k8++) {
            int r = wm * 64 + (k8 >> 1) * 16 + g + (k8 & 1) * 8;
            smf[r * 4 + wn]       = pm[k8];
            smf[512 + r * 4 + wn] = pd[k8];
        }
    }
    __syncthreads();
    if (tid < 128) {
        float m = -1e30f, d = 0.0f;
        #pragma unroll
        for (int w = 0; w < 4; w++)
            sm_merge(m, d, smf[tid * 4 + w], smf[512 + tid * 4 + w]);
        size_t o = (((size_t)b * 16 + jt) << 11) + s0 + tid;
        g_pm[o] = m;
        g_pd[o] = d;
    }
}

// ---------------------------------------------------------------------------
// K4: split-K out partials; in-block stats merge + cp.async-staged fp32 ST
// (round-14 proven). grid = (T/128, NS, B), dyn smem 68608 B, 2 CTAs/SM.
// ---------------------------------------------------------------------------
__global__ __launch_bounds__(256, 2) void out_mma_kernel()
{
    const int b  = blockIdx.z;
    const int t0 = blockIdx.x * 128;
    const int js = blockIdx.y;

    const int s_begin = js * SLEN;
    const int s_end_v = (js + 1) * SLEN;
    const int s_end   = (s_end_v < t0 + 128) ? s_end_v : (t0 + 128);
    if (s_begin >= s_end) return;

    extern __shared__ __align__(16) uint8_t dynsmem[];
    __nv_bfloat16* smem = reinterpret_cast<__nv_bfloat16*>(dynsmem);
    __shared__ float sm_m[SLEN], sm_rd[SLEN];

    const float* stb = g_st + (size_t)b * TT * TT;
    const __nv_bfloat16* vhi = g_vhi + (size_t)b * TT * HH;
    const __nv_bfloat16* vlo = g_vlo + (size_t)b * TT * HH;
    float* part = g_part + ((size_t)js * BB + b) * TT * HH;

    const int tid  = threadIdx.x;
    const int wid  = tid >> 5;
    const int lane = tid & 31;
    const int wm   = wid & 1;
    const int wn   = wid >> 1;
    const uint32_t sbase = smem_u32(dynsmem);

    auto load_st = [&](int sc, int st01) {
        uint32_t sfb = sbase + O_STF + (uint32_t)st01 * O_STF_SZ;
        #pragma unroll
        for (int i = 0; i < 4; i++) {
            int v = tid + i * 256;
            int r = v >> 5, c = v & 31;
            cp16(sfb + (uint32_t)(r * PADS + c * 4) * 4,
                 stb + (size_t)(sc + r) * TT + t0 + c * 4);
        }
    };

    load_st(s_begin, 0);
    CP_COMMIT();
    {
        int s = s_begin + tid;
        if (s < s_end) {
            float m = -1e30f, d = 0.0f;
            for (int jt = s >> 7; jt < 16; jt++) {
                size_t o = (((size_t)b * 16 + jt) << 11) + s;
                sm_merge(m, d, g_pm[o], g_pd[o]);
            }
            sm_m[tid]  = m;
            sm_rd[tid] = 1.0f / d;
        }
    }

    float acc[4][4][4] = {};
    const int nch = (s_end - s_begin) >> 5;

    for (int ch = 0; ch < nch; ch++) {
        const int sc = s_begin + ch * 32;
        const int lbase = sc - s_begin;
        const int stage = ch & 1;

        CP_WAIT0();
        __syncthreads();

        if (ch + 1 < nch) {
            load_st(sc + 32, stage ^ 1);
            CP_COMMIT();
        }

        #pragma unroll
        for (int i = 0; i < 2; i++) {
            int v = tid + i * 256;
            int r = v >> 4, c = v & 15;
            *reinterpret_cast<uint4*>(smem + O_VHI / 2 + r * PADT + c * 8) =
                *reinterpret_cast<const uint4*>(vhi + (size_t)(sc + r) * HH + c * 8);
            *reinterpret_cast<uint4*>(smem + O_VLO / 2 + r * PADT + c * 8) =
                *reinterpret_cast<const uint4*>(vlo + (size_t)(sc + r) * HH + c * 8);
        }
        const float* stf = reinterpret_cast<const float*>(
            dynsmem + O_STF + (uint32_t)stage * O_STF_SZ);
        #pragma unroll
        for (int i = 0; i < 16; i++) {
            int idx = tid + i * 256;
            int ss = idx >> 7, ttl = idx & 127;
            float val = stf[ss * PADS + ttl];
            float p = __expf(val - sm_m[lbase + ss]) * sm_rd[lbase + ss];
            __nv_bfloat16 hi = __float2bfloat16(p);
            __nv_bfloat16 lo = __float2bfloat16(p - __bfloat162float(hi));
            smem[O_PHI / 2 + ss * PADT + ttl] = hi;
            smem[O_PLO / 2 + ss * PADT + ttl] = lo;
        }
        __syncthreads();

        #pragma unroll
        for (int ks = 0; ks < 2; ks++) {
            const int k0 = ks * 16;
            uint32_t a_hi[4][4], a_lo[4][4], b_hi[2][4], b_lo[2][4];

            const int arow = k0 + (lane & 7) + ((lane >> 4) << 3);
            const int acoff = ((lane >> 3) & 1) * 8;
            #pragma unroll
            for (int i = 0; i < 4; i++) {
                uint32_t off = (uint32_t)(arow * PADT + wm * 64 + i * 16 + acoff) * 2;
                ldsm4t(a_hi[i], sbase + O_PHI + off);
                ldsm4t(a_lo[i], sbase + O_PLO + off);
            }

            const int brow = k0 + (lane & 7) + (((lane >> 3) & 1) << 3);
            const int bcoff = ((lane >> 4) << 3);
            #pragma unroll
            for (int j = 0; j < 2; j++) {
                uint32_t off = (uint32_t)(brow * PADT + wn * 32 + j * 16 + bcoff) * 2;
                ldsm4t(b_hi[j], sbase + O_VHI + off);
                ldsm4t(b_lo[j], sbase + O_VLO + off);
            }

            #pragma unroll
            for (int i = 0; i < 4; i++) {
                #pragma unroll
                for (int jn = 0; jn < 4; jn++) {
                    uint32_t b0h = b_hi[jn >> 1][(jn & 1) * 2];
                    uint32_t b1h = b_hi[jn >> 1][(jn & 1) * 2 + 1];
                    uint32_t b0l = b_lo[jn >> 1][(jn & 1) * 2];
                    uint32_t b1l = b_lo[jn >> 1][(jn & 1) * 2 + 1];
                    mma16816(acc[i][jn], a_hi[i], b0h, b1h);   // hh
                    mma16816(acc[i][jn], a_lo[i], b0h, b1h);   // lh
                    mma16816(acc[i][jn], a_hi[i], b0l, b1l);   // hl
                }
            }
        }
    }

    const int g  = lane >> 2;
    const int c2 = (lane & 3) * 2;
    #pragma unroll
    for (int i = 0; i < 4; i++) {
        #pragma unroll
        for (int jn = 0; jn < 4; jn++) {
            int t = t0 + wm * 64 + i * 16 + g;
            int h = wn * 32 + jn * 8 + c2;
            #pragma unroll
            for (int erow = 0; erow < 2; erow++) {
                float2 w;
                w.x = acc[i][jn][erow * 2];
                w.y = acc[i][jn][erow * 2 + 1];
                *reinterpret_cast<float2*>(
                    &part[(size_t)(t + erow * 8) * HH + h]) = w;
            }
        }
    }
}

// ---------------------------------------------------------------------------
// K5: reduce partials -> out (round-14 proven)
// ---------------------------------------------------------------------------
__global__ __launch_bounds__(256) void reduce_kernel(float* __restrict__ out)
{
    const int idx = blockIdx.x * 256 + threadIdx.x;
    const int h = idx & (HH - 1);
    const int t = (idx >> 7) & (TT - 1);
    const int b = idx >> 18;

    const int tile_end = ((t >> 7) + 1) << 7;
    const int nact = (tile_end + SLEN - 1) / SLEN;

    float sum = 0.0f;
    const size_t off = (size_t)b * TT * HH + (size_t)t * HH + h;
    #pragma unroll 4
    for (int j = 0; j < nact; j++)
        sum += g_part[(size_t)j * BB * TT * HH + off];
    out[idx] = sum;
}

extern "C" void kernel_launch(void* const* d_in, const int* in_sizes, int n_in,
                              void* d_out, int out_size)
{
    const float* x  = (const float*)d_in[0];
    const float* Wq = (const float*)d_in[1];
    const float* Wk = (const float*)d_in[2];
    const float* Wv = (const float*)d_in[3];
    float* out = (float*)d_out;

    cudaFuncSetAttribute(qkv_mma_kernel,
                         cudaFuncAttributeMaxDynamicSharedMemorySize, SMEM_QKV);
    cudaFuncSetAttribute(st_mma_kernel,
                         cudaFuncAttributeMaxDynamicSharedMemorySize, SMEM_DYN);
    cudaFuncSetAttribute(out_mma_kernel,
                         cudaFuncAttributeMaxDynamicSharedMemorySize, SMEM_OUT);

    prep_kernel<<<NXB + NWB, 256>>>(x, Wq, Wk, Wv);
    qkv_mma_kernel<<<dim3((BB * TT) / 64, 3), 256, SMEM_QKV>>>();
    st_mma_kernel<<<dim3(136, BB), 256, SMEM_DYN>>>();
    out_mma_kernel<<<dim3(TT / 128, NS, BB), 256, SMEM_OUT>>>();
    reduce_kernel<<<(BB * TT * HH) / 256, 256>>>(out);
}